// round 2
// baseline (speedup 1.0000x reference)
#include <cuda_runtime.h>

#define NN 2048
#define NE 65536
#define NVIEWS 6
#define C 32

// ---- scratch (no allocation allowed) ----
__device__ float g_agg[NN * C];
__device__ int   g_cnt[NN];
__device__ float g_h1[NN * C];
__device__ float g_h2[NN * C];
__device__ float g_h3[NN * C];

// ---- zero agg (+optionally cnt) ----
__global__ void zero_kernel(int zero_cnt) {
    int i = blockIdx.x * blockDim.x + threadIdx.x;
    if (i < NN * C) g_agg[i] = 0.f;
    if (zero_cnt && i < NN) g_cnt[i] = 0;
}

// ---- layer 1 edge: in_c = 1. One warp per edge. Also counts degree. ----
__global__ void edge1_kernel(const float* __restrict__ x,
                             const int* __restrict__ ei,
                             const float* __restrict__ ea,
                             const float* __restrict__ W1,
                             const float* __restrict__ b1) {
    int gid  = blockIdx.x * blockDim.x + threadIdx.x;
    int e    = gid >> 5;
    int lane = gid & 31;
    if (e >= NE) return;
    float aval = (lane < NVIEWS) ? ea[e * NVIEWS + lane] : 0.f;
    int src = ei[e];
    int dst = ei[NE + e];
    float xs = __ldg(&x[src]);
    float wr = __ldg(&b1[lane]);
#pragma unroll
    for (int v = 0; v < NVIEWS; v++)
        wr = fmaf(__shfl_sync(0xffffffffu, aval, v), __ldg(&W1[v * C + lane]), wr);
    atomicAdd(&g_agg[dst * C + lane], xs * fmaxf(wr, 0.f));
    if (lane == 0) atomicAdd(&g_cnt[dst], 1);
}

// ---- node update 1: h1 = relu(agg/max(cnt,1) + x*root1 + bias1) ----
__global__ void node1_kernel(const float* __restrict__ x,
                             const float* __restrict__ root1,
                             const float* __restrict__ bias1) {
    int idx = blockIdx.x * blockDim.x + threadIdx.x;  // NN*C threads
    int n = idx >> 5, o = idx & 31;
    float inv = 1.f / fmaxf((float)g_cnt[n], 1.f);
    float v = fmaf(g_agg[idx], inv, fmaf(x[n], root1[o], bias1[o]));
    g_h1[idx] = fmaxf(v, 0.f);
}

// ---- heavy edge layer (in_c = 32): fused edge-MLP + relu + per-edge matvec + scatter.
// One warp handles T=4 edges; lane = output channel o. W cached in smem once per block,
// each smem W element reused across the 4 edges (keeps kernel FMA-bound, not LDS-bound).
#define TEDGE 4
__global__ __launch_bounds__(256)
void edge_heavy_kernel(int hin_sel,
                       const int* __restrict__ ei,
                       const float* __restrict__ ea,
                       const float* __restrict__ W,
                       const float* __restrict__ b) {
    __shared__ float Ws[NVIEWS * 1024];
    __shared__ float bs[1024];
    for (int i = threadIdx.x; i < NVIEWS * 1024; i += blockDim.x) Ws[i] = W[i];
    for (int i = threadIdx.x; i < 1024; i += blockDim.x) bs[i] = b[i];
    __syncthreads();

    const float* __restrict__ h = (hin_sel == 1) ? g_h1 : g_h2;

    int lane = threadIdx.x & 31;
    int warp = (blockIdx.x * blockDim.x + threadIdx.x) >> 5;
    int base = warp * TEDGE;
    if (base >= NE) return;

    // 24 contiguous edge_attr floats for 4 edges -> distribute via shfl
    float aval = (lane < TEDGE * NVIEWS) ? ea[base * NVIEWS + lane] : 0.f;
    float a[TEDGE][NVIEWS];
#pragma unroll
    for (int t = 0; t < TEDGE; t++)
#pragma unroll
        for (int v = 0; v < NVIEWS; v++)
            a[t][v] = __shfl_sync(0xffffffffu, aval, t * NVIEWS + v);

    int srci = 0, dsti = 0;
    if (lane < TEDGE) {
        srci = ei[base + lane];
        dsti = ei[NE + base + lane];
    }

    float hs[TEDGE];
#pragma unroll
    for (int t = 0; t < TEDGE; t++) {
        int s = __shfl_sync(0xffffffffu, srci, t);
        hs[t] = h[s * C + lane];
    }

    float acc[TEDGE] = {0.f, 0.f, 0.f, 0.f};
#pragma unroll 4
    for (int i = 0; i < C; i++) {
        float wb  = bs[(i << 5) + lane];
        float wv0 = Ws[0 * 1024 + (i << 5) + lane];
        float wv1 = Ws[1 * 1024 + (i << 5) + lane];
        float wv2 = Ws[2 * 1024 + (i << 5) + lane];
        float wv3 = Ws[3 * 1024 + (i << 5) + lane];
        float wv4 = Ws[4 * 1024 + (i << 5) + lane];
        float wv5 = Ws[5 * 1024 + (i << 5) + lane];
#pragma unroll
        for (int t = 0; t < TEDGE; t++) {
            float wr = wb;
            wr = fmaf(a[t][0], wv0, wr);
            wr = fmaf(a[t][1], wv1, wr);
            wr = fmaf(a[t][2], wv2, wr);
            wr = fmaf(a[t][3], wv3, wr);
            wr = fmaf(a[t][4], wv4, wr);
            wr = fmaf(a[t][5], wv5, wr);
            wr = fmaxf(wr, 0.f);
            acc[t] = fmaf(__shfl_sync(0xffffffffu, hs[t], i), wr, acc[t]);
        }
    }
#pragma unroll
    for (int t = 0; t < TEDGE; t++) {
        int d = __shfl_sync(0xffffffffu, dsti, t);
        atomicAdd(&g_agg[d * C + lane], acc[t]);
    }
}

// ---- node update 2/3: h_out = relu(agg/max(cnt,1) + h_in@root + bias). Warp per node. ----
__global__ void nodeM_kernel(int sel,
                             const float* __restrict__ root,
                             const float* __restrict__ bias) {
    __shared__ float rs[1024];
    for (int i = threadIdx.x; i < 1024; i += blockDim.x) rs[i] = root[i];
    __syncthreads();
    const float* __restrict__ hin = (sel == 1) ? g_h1 : g_h2;
    float* __restrict__ hout      = (sel == 1) ? g_h2 : g_h3;

    int warp = (blockIdx.x * blockDim.x + threadIdx.x) >> 5;
    int lane = threadIdx.x & 31;
    if (warp >= NN) return;
    float hval = hin[warp * C + lane];
    float inv  = 1.f / fmaxf((float)g_cnt[warp], 1.f);
    float acc  = fmaf(g_agg[warp * C + lane], inv, bias[lane]);
#pragma unroll
    for (int i = 0; i < C; i++)
        acc = fmaf(__shfl_sync(0xffffffffu, hval, i), rs[(i << 5) + lane], acc);
    hout[warp * C + lane] = fmaxf(acc, 0.f);
}

// ---- CBT: all-pairs L1 distance. 64x64 tile per block, 4x4 register micro-tile. ----
__global__ __launch_bounds__(256)
void cbt_kernel(float* __restrict__ out) {
    __shared__ float hi[64][33];
    __shared__ float hj[64][33];
    int i0 = blockIdx.y * 64;
    int j0 = blockIdx.x * 64;
    int tid  = threadIdx.x;
    int lane = tid & 31;
    int rrow = tid >> 5;  // 0..7
#pragma unroll
    for (int r = 0; r < 8; r++) {
        hi[r * 8 + rrow][lane] = g_h3[(i0 + r * 8 + rrow) * C + lane];
        hj[r * 8 + rrow][lane] = g_h3[(j0 + r * 8 + rrow) * C + lane];
    }
    __syncthreads();

    int tx = tid & 15;   // j tile
    int ty = tid >> 4;   // i tile
    float acc[4][4];
#pragma unroll
    for (int aa = 0; aa < 4; aa++)
#pragma unroll
        for (int bb = 0; bb < 4; bb++) acc[aa][bb] = 0.f;

#pragma unroll 8
    for (int k = 0; k < C; k++) {
        float ai[4], bj[4];
#pragma unroll
        for (int aa = 0; aa < 4; aa++) ai[aa] = hi[ty * 4 + aa][k];
#pragma unroll
        for (int bb = 0; bb < 4; bb++) bj[bb] = hj[tx * 4 + bb][k];
#pragma unroll
        for (int aa = 0; aa < 4; aa++)
#pragma unroll
            for (int bb = 0; bb < 4; bb++)
                acc[aa][bb] += fabsf(ai[aa] - bj[bb]);
    }
#pragma unroll
    for (int aa = 0; aa < 4; aa++) {
        float4 v = make_float4(acc[aa][0], acc[aa][1], acc[aa][2], acc[aa][3]);
        *(float4*)&out[(size_t)(i0 + ty * 4 + aa) * NN + j0 + tx * 4] = v;
    }
}

extern "C" void kernel_launch(void* const* d_in, const int* in_sizes, int n_in,
                              void* d_out, int out_size) {
    const float* x     = (const float*)d_in[0];
    const float* ea    = (const float*)d_in[1];
    const int*   ei    = (const int*)d_in[2];
    const float* W1    = (const float*)d_in[3];
    const float* b1    = (const float*)d_in[4];
    const float* root1 = (const float*)d_in[5];
    const float* bias1 = (const float*)d_in[6];
    const float* W2    = (const float*)d_in[7];
    const float* b2    = (const float*)d_in[8];
    const float* root2 = (const float*)d_in[9];
    const float* bias2 = (const float*)d_in[10];
    const float* W3    = (const float*)d_in[11];
    const float* b3    = (const float*)d_in[12];
    const float* root3 = (const float*)d_in[13];
    const float* bias3 = (const float*)d_in[14];
    float* out = (float*)d_out;

    // layer 1
    zero_kernel<<<256, 256>>>(1);
    edge1_kernel<<<(NE * 32) / 256, 256>>>(x, ei, ea, W1, b1);
    node1_kernel<<<(NN * C) / 256, 256>>>(x, root1, bias1);
    // layer 2
    zero_kernel<<<256, 256>>>(0);
    edge_heavy_kernel<<<(NE / TEDGE) * 32 / 256, 256>>>(1, ei, ea, W2, b2);
    nodeM_kernel<<<(NN * 32) / 256, 256>>>(1, root2, bias2);
    // layer 3
    zero_kernel<<<256, 256>>>(0);
    edge_heavy_kernel<<<(NE / TEDGE) * 32 / 256, 256>>>(2, ei, ea, W3, b3);
    nodeM_kernel<<<(NN * 32) / 256, 256>>>(2, root3, bias3);
    // CBT
    cbt_kernel<<<dim3(NN / 64, NN / 64), 256>>>(out);
}

// round 3
// speedup vs baseline: 1.0645x; 1.0645x over previous
#include <cuda_runtime.h>

#define NN 2048
#define NE 65536
#define NVIEWS 6
#define C 32

typedef unsigned long long ull;

// ---- scratch (no allocation allowed). Invariant: g_agg == 0 and g_cnt == 0
// at the start of every kernel_launch (true at program load; every consumer
// kernel restores zeros after reading). ----
__device__ float g_agg[NN * C];
__device__ int   g_cnt[NN];
__device__ float g_inv[NN];
__device__ float g_h1[NN * C];
__device__ float g_h2[NN * C];
__device__ float g_h3[NN * C];

// ---- f32x2 helpers ----
__device__ __forceinline__ ull pk(float lo, float hi) {
    ull r; asm("mov.b64 %0, {%1,%2};" : "=l"(r) : "f"(lo), "f"(hi)); return r;
}
__device__ __forceinline__ void upk(ull v, float& lo, float& hi) {
    asm("mov.b64 {%0,%1}, %2;" : "=f"(lo), "=f"(hi) : "l"(v));
}
__device__ __forceinline__ ull fma2(ull a, ull b, ull c) {
    ull d; asm("fma.rn.f32x2 %0,%1,%2,%3;" : "=l"(d) : "l"(a), "l"(b), "l"(c)); return d;
}
__device__ __forceinline__ ull add2(ull a, ull b) {
    ull d; asm("add.rn.f32x2 %0,%1,%2;" : "=l"(d) : "l"(a), "l"(b)); return d;
}

// ---- layer 1 edge: in_c = 1. One warp per edge. Also counts degree. ----
__global__ void edge1_kernel(const float* __restrict__ x,
                             const int* __restrict__ ei,
                             const float* __restrict__ ea,
                             const float* __restrict__ W1,
                             const float* __restrict__ b1) {
    int gid  = blockIdx.x * blockDim.x + threadIdx.x;
    int e    = gid >> 5;
    int lane = gid & 31;
    if (e >= NE) return;
    float aval = (lane < NVIEWS) ? ea[e * NVIEWS + lane] : 0.f;
    int src = ei[e];
    int dst = ei[NE + e];
    float xs = __ldg(&x[src]);
    float wr = __ldg(&b1[lane]);
#pragma unroll
    for (int v = 0; v < NVIEWS; v++)
        wr = fmaf(__shfl_sync(0xffffffffu, aval, v), __ldg(&W1[v * C + lane]), wr);
    atomicAdd(&g_agg[dst * C + lane], xs * fmaxf(wr, 0.f));
    if (lane == 0) atomicAdd(&g_cnt[dst], 1);
}

// ---- node update 1: h1 = relu(agg/max(cnt,1) + x*root1 + bias1).
// Also: store g_inv, restore g_agg/g_cnt to zero. ----
__global__ void node1_kernel(const float* __restrict__ x,
                             const float* __restrict__ root1,
                             const float* __restrict__ bias1) {
    int idx = blockIdx.x * blockDim.x + threadIdx.x;  // NN*C threads
    int n = idx >> 5, o = idx & 31;
    float inv = 1.f / fmaxf((float)g_cnt[n], 1.f);
    float v = fmaf(g_agg[idx], inv, fmaf(x[n], root1[o], bias1[o]));
    g_h1[idx] = fmaxf(v, 0.f);
    g_agg[idx] = 0.f;
    if (o == 0) { g_inv[n] = inv; g_cnt[n] = 0; }
}

// ---- heavy edge layer (in_c = 32), f32x2-packed over edge pairs.
// Each warp handles TE=16 edges (NP=8 packed pairs); lane = output channel o.
// W & bias duplicated (w,w) in smem -> one LDS.64 feeds both halves of fma2.
// h source rows stored as packed pairs in smem -> broadcast LDS.64, no shfl
// in the inner loop. ----
#define TE 16
#define NP 8
extern __shared__ ull smem_dyn[];  // [7*1024] Wd (rows 0..5 = W, row 6 = bias) + [8*NP*32] hp

__global__ __launch_bounds__(256, 1)
void edge_heavy_kernel(int hin_sel,
                       const int* __restrict__ ei,
                       const float* __restrict__ ea,
                       const float* __restrict__ W,
                       const float* __restrict__ b) {
    ull* Wd = smem_dyn;
    ull* hp = smem_dyn + 7 * 1024;
    for (int i = threadIdx.x; i < 6 * 1024; i += 256) { float w = W[i]; Wd[i] = pk(w, w); }
    for (int i = threadIdx.x; i < 1024; i += 256)     { float w = b[i]; Wd[6 * 1024 + i] = pk(w, w); }
    __syncthreads();

    const float* __restrict__ h = (hin_sel == 1) ? g_h1 : g_h2;

    int lane = threadIdx.x & 31;
    int w    = threadIdx.x >> 5;
    int base = (blockIdx.x * 8 + w) * TE;

    // 96 contiguous edge_attr floats for 16 edges -> 3 rounds, distribute via shfl
    float av0 = ea[base * NVIEWS + lane];
    float av1 = ea[base * NVIEWS + 32 + lane];
    float av2 = ea[base * NVIEWS + 64 + lane];
    float av[3] = {av0, av1, av2};

    ull a2[NP][NVIEWS];
#pragma unroll
    for (int p = 0; p < NP; p++)
#pragma unroll
        for (int v = 0; v < NVIEWS; v++) {
            const int f0 = (2 * p) * NVIEWS + v;
            const int f1 = (2 * p + 1) * NVIEWS + v;
            float x0 = __shfl_sync(0xffffffffu, av[f0 >> 5], f0 & 31);
            float x1 = __shfl_sync(0xffffffffu, av[f1 >> 5], f1 & 31);
            a2[p][v] = pk(x0, x1);
        }

    int srci = 0, dsti = 0;
    if (lane < TE) {
        srci = ei[base + lane];
        dsti = ei[NE + base + lane];
    }

    // gather h rows for the 16 source nodes, store as packed pairs
#pragma unroll
    for (int p = 0; p < NP; p++) {
        int s0 = __shfl_sync(0xffffffffu, srci, 2 * p);
        int s1 = __shfl_sync(0xffffffffu, srci, 2 * p + 1);
        hp[(w * NP + p) * 32 + lane] = pk(h[s0 * C + lane], h[s1 * C + lane]);
    }
    __syncwarp();

    ull acc2[NP];
#pragma unroll
    for (int p = 0; p < NP; p++) acc2[p] = 0ull;

#pragma unroll 8
    for (int i = 0; i < C; i++) {
        ull wb  = Wd[6 * 1024 + (i << 5) + lane];
        ull wv0 = Wd[0 * 1024 + (i << 5) + lane];
        ull wv1 = Wd[1 * 1024 + (i << 5) + lane];
        ull wv2 = Wd[2 * 1024 + (i << 5) + lane];
        ull wv3 = Wd[3 * 1024 + (i << 5) + lane];
        ull wv4 = Wd[4 * 1024 + (i << 5) + lane];
        ull wv5 = Wd[5 * 1024 + (i << 5) + lane];
#pragma unroll
        for (int p = 0; p < NP; p++) {
            ull wr = wb;
            wr = fma2(a2[p][0], wv0, wr);
            wr = fma2(a2[p][1], wv1, wr);
            wr = fma2(a2[p][2], wv2, wr);
            wr = fma2(a2[p][3], wv3, wr);
            wr = fma2(a2[p][4], wv4, wr);
            wr = fma2(a2[p][5], wv5, wr);
            float lo, hi; upk(wr, lo, hi);
            lo = fmaxf(lo, 0.f);
            hi = fmaxf(hi, 0.f);
            ull hh = hp[(w * NP + p) * 32 + i];
            acc2[p] = fma2(hh, pk(lo, hi), acc2[p]);
        }
    }

#pragma unroll
    for (int p = 0; p < NP; p++) {
        int d0 = __shfl_sync(0xffffffffu, dsti, 2 * p);
        int d1 = __shfl_sync(0xffffffffu, dsti, 2 * p + 1);
        float lo, hi; upk(acc2[p], lo, hi);
        atomicAdd(&g_agg[d0 * C + lane], lo);
        atomicAdd(&g_agg[d1 * C + lane], hi);
    }
}

// ---- node update 2/3: h_out = relu(agg*inv + h_in@root + bias). Warp per node.
// Restores g_agg to zero after reading. ----
__global__ void nodeM_kernel(int sel,
                             const float* __restrict__ root,
                             const float* __restrict__ bias) {
    __shared__ float rs[1024];
    for (int i = threadIdx.x; i < 1024; i += blockDim.x) rs[i] = root[i];
    __syncthreads();
    const float* __restrict__ hin = (sel == 1) ? g_h1 : g_h2;
    float* __restrict__ hout      = (sel == 1) ? g_h2 : g_h3;

    int warp = (blockIdx.x * blockDim.x + threadIdx.x) >> 5;
    int lane = threadIdx.x & 31;
    if (warp >= NN) return;
    float hval = hin[warp * C + lane];
    float acc  = fmaf(g_agg[warp * C + lane], g_inv[warp], bias[lane]);
    g_agg[warp * C + lane] = 0.f;
#pragma unroll
    for (int i = 0; i < C; i++)
        acc = fmaf(__shfl_sync(0xffffffffu, hval, i), rs[(i << 5) + lane], acc);
    hout[warp * C + lane] = fmaxf(acc, 0.f);
}

// ---- CBT: all-pairs L1 distance. 64x64 tile per block, 4x4 micro-tile,
// f32x2 packed: |a-b| = (a + (-b)) & 0x7FFF..., splitting fma/alu pipes. ----
__global__ __launch_bounds__(256)
void cbt_kernel(float* __restrict__ out) {
    __shared__ ull hiD[32 * 65];                     // [k][i] duplicated (v,v), pad 65
    __shared__ __align__(16) float hjN[32 * 66];     // [k][j] negated, pad 66 (even)
    int tid = threadIdx.x, lane = tid & 31, wrow = tid >> 5;
    int i0 = blockIdx.y * 64, j0 = blockIdx.x * 64;
#pragma unroll
    for (int r = 0; r < 8; r++) {
        int n = wrow * 8 + r;
        float vi = g_h3[(i0 + n) * C + lane];
        hiD[lane * 65 + n] = pk(vi, vi);
        float vj = g_h3[(j0 + n) * C + lane];
        hjN[lane * 66 + n] = -vj;
    }
    __syncthreads();

    int tx = tid & 15;   // j group (4 cols)
    int ty = tid >> 4;   // i group (4 rows)
    ull acc2[4][2];
#pragma unroll
    for (int aa = 0; aa < 4; aa++) { acc2[aa][0] = 0ull; acc2[aa][1] = 0ull; }

    const ull MASK = 0x7FFFFFFF7FFFFFFFULL;
#pragma unroll 8
    for (int k = 0; k < C; k++) {
        ull aj0 = *(const ull*)&hjN[k * 66 + tx * 4];
        ull aj1 = *(const ull*)&hjN[k * 66 + tx * 4 + 2];
#pragma unroll
        for (int aa = 0; aa < 4; aa++) {
            ull ai = hiD[k * 65 + ty * 4 + aa];
            ull d0 = add2(ai, aj0) & MASK;
            ull d1 = add2(ai, aj1) & MASK;
            acc2[aa][0] = add2(acc2[aa][0], d0);
            acc2[aa][1] = add2(acc2[aa][1], d1);
        }
    }
#pragma unroll
    for (int aa = 0; aa < 4; aa++) {
        float a0, a1, a2v, a3;
        upk(acc2[aa][0], a0, a1);
        upk(acc2[aa][1], a2v, a3);
        *(float4*)&out[(size_t)(i0 + ty * 4 + aa) * NN + j0 + tx * 4] =
            make_float4(a0, a1, a2v, a3);
    }
}

extern "C" void kernel_launch(void* const* d_in, const int* in_sizes, int n_in,
                              void* d_out, int out_size) {
    const float* x     = (const float*)d_in[0];
    const float* ea    = (const float*)d_in[1];
    const int*   ei    = (const int*)d_in[2];
    const float* W1    = (const float*)d_in[3];
    const float* b1    = (const float*)d_in[4];
    const float* root1 = (const float*)d_in[5];
    const float* bias1 = (const float*)d_in[6];
    const float* W2    = (const float*)d_in[7];
    const float* b2    = (const float*)d_in[8];
    const float* root2 = (const float*)d_in[9];
    const float* bias2 = (const float*)d_in[10];
    const float* W3    = (const float*)d_in[11];
    const float* b3    = (const float*)d_in[12];
    const float* root3 = (const float*)d_in[13];
    const float* bias3 = (const float*)d_in[14];
    float* out = (float*)d_out;

    // dynamic smem for edge_heavy: Wd 7*1024*8 + hp 8*NP*32*8 = 57344 + 16384
    static const int EH_SMEM = (7 * 1024 + 8 * NP * 32) * (int)sizeof(ull);
    cudaFuncSetAttribute(edge_heavy_kernel,
                         cudaFuncAttributeMaxDynamicSharedMemorySize, EH_SMEM);

    // layer 1 (g_agg/g_cnt are zero on entry by invariant)
    edge1_kernel<<<(NE * 32) / 256, 256>>>(x, ei, ea, W1, b1);
    node1_kernel<<<(NN * C) / 256, 256>>>(x, root1, bias1);
    // layer 2
    edge_heavy_kernel<<<NE / (8 * TE), 256, EH_SMEM>>>(1, ei, ea, W2, b2);
    nodeM_kernel<<<(NN * 32) / 256, 256>>>(1, root2, bias2);
    // layer 3
    edge_heavy_kernel<<<NE / (8 * TE), 256, EH_SMEM>>>(2, ei, ea, W3, b3);
    nodeM_kernel<<<(NN * 32) / 256, 256>>>(2, root3, bias3);
    // CBT
    cbt_kernel<<<dim3(NN / 64, NN / 64), 256>>>(out);
}